// round 6
// baseline (speedup 1.0000x reference)
#include <cuda_runtime.h>
#include <cuda_bf16.h>

#define NQ        12
#define BLK       128
#define OUTDIM    256
#define HID       64

__device__ __forceinline__ float2 cmul(float2 a, float2 b) {
    return make_float2(a.x * b.x - a.y * b.y, a.x * b.y + a.y * b.x);
}

__device__ __forceinline__ float2 cfma2(float2 ca, float2 a, float2 cb, float2 b) {
    float2 n;
    n.x = ca.x * a.x - ca.y * a.y + cb.x * b.x - cb.y * b.y;
    n.y = ca.x * a.y + ca.y * a.x + cb.x * b.y + cb.y * b.x;
    return n;
}

__device__ __forceinline__ float2 shflx(float2 v, int m) {
    float2 r;
    r.x = __shfl_xor_sync(0xFFFFFFFFu, v.x, m);
    r.y = __shfl_xor_sync(0xFFFFFFFFu, v.y, m);
    return r;
}

// CNOT-ring composite: out bit p (p<=10) = XOR of in bits p..11; bit 11 = XOR of bits 0..10.
__host__ __device__ constexpr int Lmap(int b) {
    int r = 0;
    for (int p = 0; p <= 10; p++) {
        int par = 0;
        for (int q = p; q <= 11; q++) par ^= (b >> q) & 1;
        r |= par << p;
    }
    int par = 0;
    for (int q = 0; q <= 10; q++) par ^= (b >> q) & 1;
    return r | (par << 11);
}
__host__ __device__ constexpr int swzc(int x) { return x ^ (((x >> 5) & 15) << 1); }
struct PKt { int v[32]; };
__host__ __device__ constexpr PKt mkPK() {
    PKt t{};
    for (int k = 0; k < 32; k++) t.v[k] = swzc(Lmap(k << 7));
    return t;
}

__global__ __launch_bounds__(BLK) void quantum_reupload_kernel(
    const float* __restrict__ x,    // [B, 48]
    const float* __restrict__ rw,   // [12, 3, 4]
    const float* __restrict__ rb,   // [12, 3]
    const float* __restrict__ w1,   // [64, 12]
    const float* __restrict__ b1,   // [64]
    const float* __restrict__ w2,   // [256, 64]
    const float* __restrict__ b2,   // [256]
    float* __restrict__ out)        // [B, 256]
{
    __shared__ float2 st[4096];          // 32 KB exchange buffer
    __shared__ float2 U[NQ][4];
    __shared__ float  zred[NQ][BLK/32];
    __shared__ float  zfin[NQ];
    __shared__ float  hbuf[HID];

    const int b    = blockIdx.x;
    const int tid  = threadIdx.x;       // 0..127
    const int lane = tid & 31;
    const int warp = tid >> 5;

    constexpr PKt PK = mkPK();          // CNOT-perm constants (swizzled), compile-time

    // ---- per-batch U3 matrices (layer-invariant) ----
    if (tid < NQ) {
        const float* xb  = x  + b * 48 + tid * 4;
        const float* rwi = rw + tid * 12;
        const float* rbi = rb + tid * 3;
        float x0 = xb[0], x1 = xb[1], x2 = xb[2], x3 = xb[3];
        float th = rbi[0] + rwi[0]*x0 + rwi[1]*x1 + rwi[2] *x2 + rwi[3] *x3;
        float ph = rbi[1] + rwi[4]*x0 + rwi[5]*x1 + rwi[6] *x2 + rwi[7] *x3;
        float lm = rbi[2] + rwi[8]*x0 + rwi[9]*x1 + rwi[10]*x2 + rwi[11]*x3;
        float sh, ch, sp, cp, sl, cl;
        sincosf(th * 0.5f, &sh, &ch);
        sincosf(ph,        &sp, &cp);
        sincosf(lm,        &sl, &cl);
        U[tid][0] = make_float2(ch, 0.f);
        U[tid][1] = make_float2(-cl * sh, -sl * sh);
        U[tid][2] = make_float2( cp * sh,  sp * sh);
        U[tid][3] = make_float2((cp*cl - sp*sl) * ch, (cp*sl + sp*cl) * ch);
    }
    __syncthreads();

    // L(tid) for the low-7 index bits (suffix-parity), plus swizzle
    int y = tid; y ^= y >> 1; y ^= y >> 2; y ^= y >> 4;
    const int Ltid  = (y & 0x7F) | ((y & 1) << 11);
    const int PLtid = Ltid ^ (((Ltid >> 5) & 15) << 1);
    const int akey  = tid & 15;          // A-mapping f4 swizzle key

    float2 a[32];
    float4* st4 = (float4*)st;

    // ===== layer 0: tensor-product state in mapping B: idx=(k<<7)|tid =====
    // wire w in [5,11] <-> tid bit (11-w); wire w in [0,4] <-> k bit (4-w)
    {
        float2 base = ((tid >> 6) & 1) ? U[5][2] : U[5][0];
        #pragma unroll
        for (int w = 6; w < 12; w++)
            base = cmul(base, ((tid >> (11 - w)) & 1) ? U[w][2] : U[w][0]);
        float2 p01[4], p234[8];
        #pragma unroll
        for (int i = 0; i < 4; i++)
            p01[i] = cmul((i & 2) ? U[0][2] : U[0][0], (i & 1) ? U[1][2] : U[1][0]);
        #pragma unroll
        for (int i = 0; i < 8; i++)
            p234[i] = cmul((i & 4) ? U[2][2] : U[2][0],
                      cmul((i & 2) ? U[3][2] : U[3][0], (i & 1) ? U[4][2] : U[4][0]));
        #pragma unroll
        for (int k = 0; k < 32; k++)
            a[k] = cmul(base, cmul(p01[k >> 3], p234[k & 7]));
    }

    // CNOT-ring perm fused into write: phys(L((k<<7)|tid)) = PLtid ^ PK[k]
    #pragma unroll
    for (int k = 0; k < 32; k++)
        st[PLtid ^ PK.v[k]] = a[k];
    __syncthreads();
    // A-read (f4, swizzled): logical (tid<<5)|k
    #pragma unroll
    for (int j = 0; j < 16; j++) {
        float4 v = st4[(tid << 4) | (j ^ akey)];
        a[2*j]   = make_float2(v.x, v.y);
        a[2*j+1] = make_float2(v.z, v.w);
    }

    // ===== layers 1,2 =====
    #pragma unroll
    for (int layer = 1; layer < 3; layer++) {
        // A-phase shfl: wire 5 (lane bit 1), wire 6 (lane bit 0)
        #pragma unroll
        for (int w = 5; w < 7; w++) {
            const int lb = 6 - w;
            float2 u00 = U[w][0], u01 = U[w][1], u10 = U[w][2], u11 = U[w][3];
            bool hi = (lane >> lb) & 1;
            float2 ca = hi ? u11 : u00;
            float2 cb = hi ? u10 : u01;
            #pragma unroll
            for (int k = 0; k < 32; k++) {
                float2 p = shflx(a[k], 1 << lb);
                a[k] = cfma2(ca, a[k], cb, p);
            }
        }
        // A-phase reg: wires 7..11 on k bit (11-w)
        #pragma unroll
        for (int w = 7; w < 12; w++) {
            const int bp = 11 - w;
            float2 u00 = U[w][0], u01 = U[w][1], u10 = U[w][2], u11 = U[w][3];
            #pragma unroll
            for (int k0 = 0; k0 < 32; k0++) {
                if (k0 & (1 << bp)) continue;
                const int k1 = k0 | (1 << bp);
                float2 a0 = a[k0], a1 = a[k1];
                a[k0] = cfma2(u00, a0, u01, a1);
                a[k1] = cfma2(u10, a0, u11, a1);
            }
        }

        // transpose A -> B
        __syncthreads();
        #pragma unroll
        for (int j = 0; j < 16; j++)
            st4[(tid << 4) | (j ^ akey)] =
                make_float4(a[2*j].x, a[2*j].y, a[2*j+1].x, a[2*j+1].y);
        __syncthreads();
        #pragma unroll
        for (int k = 0; k < 32; k++) {
            const int xb = (k << 7) | tid;
            a[k] = st[xb ^ (((xb >> 5) & 15) << 1)];
        }

        // B-phase reg: wires 0..4 on k bit (4-w)
        #pragma unroll
        for (int w = 0; w < 5; w++) {
            const int bp = 4 - w;
            float2 u00 = U[w][0], u01 = U[w][1], u10 = U[w][2], u11 = U[w][3];
            #pragma unroll
            for (int k0 = 0; k0 < 32; k0++) {
                if (k0 & (1 << bp)) continue;
                const int k1 = k0 | (1 << bp);
                float2 a0 = a[k0], a1 = a[k1];
                a[k0] = cfma2(u00, a0, u01, a1);
                a[k1] = cfma2(u10, a0, u11, a1);
            }
        }

        // fused CNOT-ring perm back to mapping A
        __syncthreads();
        #pragma unroll
        for (int k = 0; k < 32; k++)
            st[PLtid ^ PK.v[k]] = a[k];
        __syncthreads();
        #pragma unroll
        for (int j = 0; j < 16; j++) {
            float4 v = st4[(tid << 4) | (j ^ akey)];
            a[2*j]   = make_float2(v.x, v.y);
            a[2*j+1] = make_float2(v.z, v.w);
        }
    }

    // ---- Pauli-Z (mapping A: idx bits 11..5 = tid, 4..0 = k) ----
    // wire w in [0,6] <-> tid bit (6-w); wire w in [7,11] <-> k bit (11-w)
    float psum = 0.f, s7 = 0.f, s8 = 0.f, s9 = 0.f, s10 = 0.f, s11 = 0.f;
    #pragma unroll
    for (int k = 0; k < 32; k++) {
        float pr = a[k].x * a[k].x + a[k].y * a[k].y;
        psum += pr;
        s7  += (k & 16) ? -pr : pr;
        s8  += (k &  8) ? -pr : pr;
        s9  += (k &  4) ? -pr : pr;
        s10 += (k &  2) ? -pr : pr;
        s11 += (k &  1) ? -pr : pr;
    }
    float zl[NQ];
    #pragma unroll
    for (int w = 0; w < 7; w++)
        zl[w] = ((tid >> (6 - w)) & 1) ? -psum : psum;
    zl[7] = s7; zl[8] = s8; zl[9] = s9; zl[10] = s10; zl[11] = s11;

    #pragma unroll
    for (int w = 0; w < NQ; w++) {
        #pragma unroll
        for (int off = 16; off > 0; off >>= 1)
            zl[w] += __shfl_xor_sync(0xFFFFFFFFu, zl[w], off);
    }
    if (lane == 0) {
        #pragma unroll
        for (int w = 0; w < NQ; w++) zred[w][warp] = zl[w];
    }
    __syncthreads();
    if (tid < NQ) {
        float z = 0.f;
        #pragma unroll
        for (int j = 0; j < BLK / 32; j++) z += zred[tid][j];
        zfin[tid] = z;
    }
    __syncthreads();

    // ---- MLP: relu(z @ w1^T + b1) @ w2^T + b2 ----
    if (tid < HID) {
        float h = b1[tid];
        #pragma unroll
        for (int i = 0; i < NQ; i++) h += zfin[i] * w1[tid * NQ + i];
        hbuf[tid] = fmaxf(h, 0.f);
    }
    __syncthreads();
    #pragma unroll
    for (int r = 0; r < OUTDIM / BLK; r++) {
        const int oi = tid + r * BLK;
        float o = b2[oi];
        #pragma unroll
        for (int j = 0; j < HID; j++) o += hbuf[j] * w2[oi * HID + j];
        out[b * OUTDIM + oi] = o;
    }
}

extern "C" void kernel_launch(void* const* d_in, const int* in_sizes, int n_in,
                              void* d_out, int out_size) {
    const float* x  = (const float*)d_in[0];
    const float* rw = (const float*)d_in[1];
    const float* rb = (const float*)d_in[2];
    const float* w1 = (const float*)d_in[3];
    const float* b1 = (const float*)d_in[4];
    const float* w2 = (const float*)d_in[5];
    const float* b2 = (const float*)d_in[6];
    float* out = (float*)d_out;
    int batch = in_sizes[0] / 48;
    quantum_reupload_kernel<<<batch, BLK>>>(x, rw, rb, w1, b1, w2, b2, out);
}

// round 7
// speedup vs baseline: 1.2258x; 1.2258x over previous
#include <cuda_runtime.h>
#include <cuda_bf16.h>

#define NQ        12
#define BLK       256
#define OUTDIM    256
#define HID       64

__device__ __forceinline__ float2 cmul(float2 a, float2 b) {
    return make_float2(a.x * b.x - a.y * b.y, a.x * b.y + a.y * b.x);
}

__device__ __forceinline__ float2 cfma2(float2 ca, float2 a, float2 cb, float2 b) {
    float2 n;
    n.x = ca.x * a.x - ca.y * a.y + cb.x * b.x - cb.y * b.y;
    n.y = ca.x * a.y + ca.y * a.x + cb.x * b.y + cb.y * b.x;
    return n;
}

__device__ __forceinline__ float2 shflx(float2 v, int m) {
    float2 r;
    r.x = __shfl_xor_sync(0xFFFFFFFFu, v.x, m);
    r.y = __shfl_xor_sync(0xFFFFFFFFu, v.y, m);
    return r;
}

// CNOT-ring composite: out bit p (p<=10) = XOR of in bits p..11; bit 11 = XOR of bits 0..10.
__host__ __device__ constexpr int Lmap(int b) {
    int r = 0;
    for (int p = 0; p <= 10; p++) {
        int par = 0;
        for (int q = p; q <= 11; q++) par ^= (b >> q) & 1;
        r |= par << p;
    }
    int par = 0;
    for (int q = 0; q <= 10; q++) par ^= (b >> q) & 1;
    return r | (par << 11);
}
__host__ __device__ constexpr int swz4(int x) { return x ^ ((x >> 4) & 15); }
struct PKt { int v[16]; };
__host__ __device__ constexpr PKt mkPK() {
    PKt t{};
    for (int k = 0; k < 16; k++) t.v[k] = swz4(Lmap(k << 8));
    return t;
}

__global__ __launch_bounds__(BLK) void quantum_reupload_kernel(
    const float* __restrict__ x,    // [B, 48]
    const float* __restrict__ rw,   // [12, 3, 4]
    const float* __restrict__ rb,   // [12, 3]
    const float* __restrict__ w1,   // [64, 12]
    const float* __restrict__ b1,   // [64]
    const float* __restrict__ w2,   // [256, 64]
    const float* __restrict__ b2,   // [256]
    float* __restrict__ out)        // [B, 256]
{
    __shared__ float2 st[4096];          // 32 KB exchange buffer
    __shared__ float2 U[NQ][4];
    __shared__ float  zred[NQ][BLK/32];
    __shared__ float  zfin[NQ];
    __shared__ float  hbuf[HID];

    const int b    = blockIdx.x;
    const int tid  = threadIdx.x;       // 0..255
    const int lane = tid & 31;
    const int warp = tid >> 5;

    constexpr PKt PK = mkPK();          // swz4(L(k<<8)) constants

    // ---- per-batch U3 matrices (layer-invariant) ----
    if (tid < NQ) {
        const float* xb  = x  + b * 48 + tid * 4;
        const float* rwi = rw + tid * 12;
        const float* rbi = rb + tid * 3;
        float x0 = xb[0], x1 = xb[1], x2 = xb[2], x3 = xb[3];
        float th = rbi[0] + rwi[0]*x0 + rwi[1]*x1 + rwi[2] *x2 + rwi[3] *x3;
        float ph = rbi[1] + rwi[4]*x0 + rwi[5]*x1 + rwi[6] *x2 + rwi[7] *x3;
        float lm = rbi[2] + rwi[8]*x0 + rwi[9]*x1 + rwi[10]*x2 + rwi[11]*x3;
        float sh, ch, sp, cp, sl, cl;
        sincosf(th * 0.5f, &sh, &ch);
        sincosf(ph,        &sp, &cp);
        sincosf(lm,        &sl, &cl);
        U[tid][0] = make_float2(ch, 0.f);
        U[tid][1] = make_float2(-cl * sh, -sl * sh);
        U[tid][2] = make_float2( cp * sh,  sp * sh);
        U[tid][3] = make_float2((cp*cl - sp*sl) * ch, (cp*sl + sp*cl) * ch);
    }
    __syncthreads();

    // L(tid part) via suffix parity over 8 bits + bit 11 = parity(tid)
    int y = tid; y ^= y >> 1; y ^= y >> 2; y ^= y >> 4;
    const int Ltid  = (y & 0xFF) | ((y & 1) << 11);
    const int PLtid = swz4(Ltid);
    const int tlo   = tid & 15;          // A-mapping swizzle key

    const int t0 = tid & 1, t1 = (tid >> 1) & 1, t2 = (tid >> 2) & 1,
              t3 = (tid >> 3) & 1, t4 = (tid >> 4) & 1, t5 = (tid >> 5) & 1,
              t6 = (tid >> 6) & 1, t7 = (tid >> 7) & 1;

    float2 a[16];

    // ===== direct build of (perm ∘ layer-0-U3) state in mapping A =====
    // A: p = (tid<<4)|k. amp_A[p] = Π_w f_w(x_{11-w}), x = L^{-1}(p):
    //   w=0: k0^t7   w=1: k0^t6^t7   w=2..7: t(9-w)^t(10-w)   (tid-only for w>=2)
    //   w=8: k3^t0   w=9: k2^k3      w=10: k1^k2   w=11: k0^k1
    {
        float2 base =      (t5 ^ t6) ? U[2][2] : U[2][0];
        base = cmul(base, ((t4 ^ t5) ? U[3][2] : U[3][0]));
        base = cmul(base, ((t3 ^ t4) ? U[4][2] : U[4][0]));
        base = cmul(base, ((t2 ^ t3) ? U[5][2] : U[5][0]));
        base = cmul(base, ((t1 ^ t2) ? U[6][2] : U[6][0]));
        base = cmul(base, ((t0 ^ t1) ? U[7][2] : U[7][0]));
        float2 baseG[2];
        #pragma unroll
        for (int k0 = 0; k0 < 2; k0++) {
            float2 g = cmul(((k0 ^ t7) ? U[0][2] : U[0][0]),
                            ((k0 ^ t6 ^ t7) ? U[1][2] : U[1][0]));
            baseG[k0] = cmul(base, g);
        }
        // m-parametrization: m3=k3, m2=k2^k3, m1=k1^k2, m0=k0^k1
        float2 Qhi[4], Qlo[4];
        #pragma unroll
        for (int i = 0; i < 4; i++) {
            int m3 = i >> 1, m2 = i & 1;
            Qhi[i] = cmul(((m3 ^ t0) ? U[8][2] : U[8][0]),
                          (m2 ? U[9][2] : U[9][0]));
            int m1 = i >> 1, m0 = i & 1;
            Qlo[i] = cmul((m1 ? U[10][2] : U[10][0]),
                          (m0 ? U[11][2] : U[11][0]));
        }
        #pragma unroll
        for (int k = 0; k < 16; k++) {
            const int k0 = k & 1, k1 = (k >> 1) & 1, k2 = (k >> 2) & 1, k3 = k >> 3;
            const int m3 = k3, m2 = k2 ^ k3, m1 = k1 ^ k2, m0 = k0 ^ k1;
            a[k] = cmul(baseG[k0], cmul(Qhi[(m3 << 1) | m2], Qlo[(m1 << 1) | m0]));
        }
    }

    // ===== layers 1,2 =====
    #pragma unroll
    for (int layer = 1; layer < 3; layer++) {
        // A-phase shfl: wires 4..7 on lane bit (7-w)
        #pragma unroll
        for (int w = 4; w < 8; w++) {
            const int lb = 7 - w;
            float2 u00 = U[w][0], u01 = U[w][1], u10 = U[w][2], u11 = U[w][3];
            bool hi = (lane >> lb) & 1;
            float2 ca = hi ? u11 : u00;
            float2 cb = hi ? u10 : u01;
            #pragma unroll
            for (int k = 0; k < 16; k++) {
                float2 p = shflx(a[k], 1 << lb);
                a[k] = cfma2(ca, a[k], cb, p);
            }
        }
        // A-phase reg: wires 8..11 on k bit (11-w)
        #pragma unroll
        for (int w = 8; w < 12; w++) {
            const int bp = 11 - w;
            float2 u00 = U[w][0], u01 = U[w][1], u10 = U[w][2], u11 = U[w][3];
            #pragma unroll
            for (int k0 = 0; k0 < 16; k0++) {
                if (k0 & (1 << bp)) continue;
                const int k1 = k0 | (1 << bp);
                float2 a0 = a[k0], a1 = a[k1];
                a[k0] = cfma2(u00, a0, u01, a1);
                a[k1] = cfma2(u10, a0, u11, a1);
            }
        }

        // transpose A -> B (R4-validated addressing)
        __syncthreads();
        #pragma unroll
        for (int k = 0; k < 16; k++)
            st[(tid << 4) | (k ^ tlo)] = a[k];
        __syncthreads();
        #pragma unroll
        for (int k = 0; k < 16; k++) {
            const int xb = (k << 8) | tid;
            a[k] = st[swz4(xb)];
        }

        // B-phase reg: wires 0..3 on k bit (3-w)
        #pragma unroll
        for (int w = 0; w < 4; w++) {
            const int bp = 3 - w;
            float2 u00 = U[w][0], u01 = U[w][1], u10 = U[w][2], u11 = U[w][3];
            #pragma unroll
            for (int k0 = 0; k0 < 16; k0++) {
                if (k0 & (1 << bp)) continue;
                const int k1 = k0 | (1 << bp);
                float2 a0 = a[k0], a1 = a[k1];
                a[k0] = cfma2(u00, a0, u01, a1);
                a[k1] = cfma2(u10, a0, u11, a1);
            }
        }

        if (layer == 1) {
            // fused CNOT-ring perm back to mapping A (R4-validated)
            __syncthreads();
            #pragma unroll
            for (int k = 0; k < 16; k++)
                st[PLtid ^ PK.v[k]] = a[k];
            __syncthreads();
            #pragma unroll
            for (int k = 0; k < 16; k++)
                a[k] = st[(tid << 4) | (k ^ tlo)];
        }
    }

    // ===== Z expectations directly in mapping B, final perm folded into signs =====
    // Z_w = sum_b parity(b & M_w) * |psi(b)|^2;  b = (k<<8)|tid.
    // k-signatures: A=k0^k1^k2 (w0), B=k2^k3 (w1), C=k1^k2^k3 (w2), D=k0^k1^k2^k3 (w>=3)
    float SA = 0.f, SB = 0.f, SC = 0.f, SD = 0.f;
    #pragma unroll
    for (int k = 0; k < 16; k++) {
        float pr = a[k].x * a[k].x + a[k].y * a[k].y;
        const int k0 = k & 1, k1 = (k >> 1) & 1, k2 = (k >> 2) & 1, k3 = k >> 3;
        SA += (k0 ^ k1 ^ k2)      ? -pr : pr;
        SB += (k2 ^ k3)           ? -pr : pr;
        SC += (k1 ^ k2 ^ k3)      ? -pr : pr;
        SD += (k0 ^ k1 ^ k2 ^ k3) ? -pr : pr;
    }
    float zl[NQ];
    {
        const int ptid = __popc(tid) & 1;          // parity of tid bits 0..7
        zl[0] = ptid ? -SA : SA;
        zl[1] = SB;
        zl[2] = SC;
        zl[3] = SD;
        #pragma unroll
        for (int w = 4; w < 12; w++) {
            const int j = 11 - w;                  // tid bits j..7
            zl[w] = (__popc(tid >> j) & 1) ? -SD : SD;
        }
    }

    #pragma unroll
    for (int w = 0; w < NQ; w++) {
        #pragma unroll
        for (int off = 16; off > 0; off >>= 1)
            zl[w] += __shfl_xor_sync(0xFFFFFFFFu, zl[w], off);
    }
    if (lane == 0) {
        #pragma unroll
        for (int w = 0; w < NQ; w++) zred[w][warp] = zl[w];
    }
    __syncthreads();
    if (tid < NQ) {
        float z = 0.f;
        #pragma unroll
        for (int j = 0; j < BLK / 32; j++) z += zred[tid][j];
        zfin[tid] = z;
    }
    __syncthreads();

    // ---- MLP: relu(z @ w1^T + b1) @ w2^T + b2 ----
    if (tid < HID) {
        float h = b1[tid];
        #pragma unroll
        for (int i = 0; i < NQ; i++) h += zfin[i] * w1[tid * NQ + i];
        hbuf[tid] = fmaxf(h, 0.f);
    }
    __syncthreads();
    float o = b2[tid];
    #pragma unroll
    for (int j = 0; j < HID; j++) o += hbuf[j] * w2[tid * HID + j];
    out[b * OUTDIM + tid] = o;
}

extern "C" void kernel_launch(void* const* d_in, const int* in_sizes, int n_in,
                              void* d_out, int out_size) {
    const float* x  = (const float*)d_in[0];
    const float* rw = (const float*)d_in[1];
    const float* rb = (const float*)d_in[2];
    const float* w1 = (const float*)d_in[3];
    const float* b1 = (const float*)d_in[4];
    const float* w2 = (const float*)d_in[5];
    const float* b2 = (const float*)d_in[6];
    float* out = (float*)d_out;
    int batch = in_sizes[0] / 48;
    quantum_reupload_kernel<<<batch, BLK>>>(x, rw, rb, w1, b1, w2, b2, out);
}